// round 9
// baseline (speedup 1.0000x reference)
#include <cuda_runtime.h>
#include <cuda_fp16.h>
#include <math.h>

// ---------------- problem constants ----------------
#define NQ      32768      // BATCH*2 query rows
#define D       128
#define G4      1024       // gate width (original order: i|f|g|o blocks of 256)
#define FEW     5
#define SST     136        // smem stride (halfs): conflict-free fragment banks

// k_gbuf smem (bytes): As 34816 | Bs 34816 | bias 4096
#define GB_OFF_BS   34816
#define GB_OFF_BIAS 69632
#define SMEM_GBUF   73728

// k_step smem (bytes): As 17408 | Bs 34816 | sS2 20480 | sAt 1280
#define ST_OFF_BS   17408
#define ST_OFF_SS2  52224
#define ST_OFF_SAT  72704
#define SMEM_STEP   73984

// ---------------- scratch (static device arrays; no allocation) ----------------
__device__ float  d_SG[FEW * D];                 // support_g (5 x 128)
__device__ float  d_S2[FEW * G4];                // SG @ W_hh[:,128:].T
__device__ float  d_MS[D];                       // mean_support
__device__ float  d_q   [(size_t)NQ * D];        // gathered query embeddings (fp32)
__device__ __half d_q16 [(size_t)NQ * D];        // fp16 q
__device__ __half d_hl16[(size_t)NQ * D];        // hl fp16 (init -q; rewritten per step)
__device__ float  d_hl  [(size_t)NQ * D];        // fp32 hl (last step only)
__device__ __half d_Gbuf[(size_t)NQ * G4];       // G01 = q@(Wih+W1).T + bsum  (fp16)
__device__ float  d_c   [(size_t)NQ * 256];      // LSTM cell state (fp32)
__device__ float  d_attn[(size_t)NQ * 8];        // attention weights (5, padded 8)
__device__ __half d_Wc16[G4 * D];                // Wih + Whh[:,:128] (fp16)
__device__ __half d_W116[G4 * D];                // Whh[:,:128]       (fp16)
__device__ float  d_bsum[G4];                    // b_ih + b_hh

__device__ __forceinline__ float sigf(float x) { return 1.0f / (1.0f + expf(-x)); }

__device__ __forceinline__ void mma_f16(float* c, const unsigned* a, unsigned b0, unsigned b1) {
    asm volatile(
        "mma.sync.aligned.m16n8k16.row.col.f32.f16.f16.f32 "
        "{%0,%1,%2,%3}, {%4,%5,%6,%7}, {%8,%9}, {%0,%1,%2,%3};"
        : "+f"(c[0]), "+f"(c[1]), "+f"(c[2]), "+f"(c[3])
        : "r"(a[0]), "r"(a[1]), "r"(a[2]), "r"(a[3]), "r"(b0), "r"(b1));
}

// ---------------- prep: fp16 weight packs / bsum ----------------
__global__ void k_wsum(const float* __restrict__ Wih, const float* __restrict__ Whh,
                       const float* __restrict__ bih, const float* __restrict__ bhh) {
    int idx = blockIdx.x * 256 + threadIdx.x;           // 1024*128
    int r = idx >> 7, k = idx & 127;
    float w1 = Whh[(size_t)r * 256 + k];
    d_Wc16[idx] = __float2half_rn(Wih[idx] + w1);
    d_W116[idx] = __float2half_rn(w1);
    if (idx < G4) d_bsum[idx] = bih[idx] + bhh[idx];
}

// ---------------- support path: GCN (linear!) + MLP + LayerNorm ----------------
__global__ void k_support(const int* __restrict__ sp, const float* __restrict__ emb,
                          const float* __restrict__ gW, const float* __restrict__ gb,
                          const float* __restrict__ p1W, const float* __restrict__ p1b,
                          const float* __restrict__ p2W, const float* __restrict__ p2b,
                          const float* __restrict__ lng, const float* __restrict__ lnb) {
    __shared__ float cs[256], s[128], h1[256], x[128], stat[2];
    int f = blockIdx.x, t = threadIdx.x;
    int side = t >> 7, col = t & 127;
    const int* pf = sp + f * 400;
    float acc = 0.f;
    #pragma unroll 4
    for (int n = 0; n < 200; n++) {
        int idx = pf[n * 2 + side];
        acc += emb[(size_t)idx * 128 + col];
    }
    cs[t] = acc;
    __syncthreads();
    if (t < 128) {
        float a = 200.f * gb[t];
        #pragma unroll 4
        for (int k = 0; k < 256; k++) a = fmaf(cs[k], gW[t * 256 + k], a);
        s[t] = tanhf(a * 0.2f);
    }
    __syncthreads();
    {
        float a = p1b[t];
        #pragma unroll 4
        for (int j = 0; j < 128; j++) a = fmaf(s[j], p1W[t * 128 + j], a);
        h1[t] = fmaxf(a, 0.f);
    }
    __syncthreads();
    if (t < 128) {
        float a = p2b[t];
        #pragma unroll 4
        for (int k = 0; k < 256; k++) a = fmaf(h1[k], p2W[t * 256 + k], a);
        x[t] = a + s[t];
    }
    __syncthreads();
    if (t == 0) {
        float mu = 0.f;
        for (int j = 0; j < 128; j++) mu += x[j];
        mu *= (1.f / 128.f);
        float v = 0.f;
        for (int j = 0; j < 128; j++) { float dd = x[j] - mu; v += dd * dd; }
        v *= (1.f / 128.f);
        stat[0] = mu; stat[1] = rsqrtf(v + 1e-5f);
    }
    __syncthreads();
    if (t < 128) d_SG[f * 128 + t] = lng[t] * (x[t] - stat[0]) * stat[1] + lnb[t];
}

// ---------------- S2 = SG @ W_hh[:,128:].T + mean_support ----------------
__global__ void k_s2mean(const float* __restrict__ Whh) {
    __shared__ float sg[128];
    int b = blockIdx.x, t = threadIdx.x;
    if (b < 40) {
        int f = b >> 3, gbk = b & 7;
        sg[t] = d_SG[f * 128 + t];
        __syncthreads();
        int g = gbk * 128 + t;
        float a = 0.f;
        #pragma unroll 4
        for (int j = 0; j < 128; j++) a = fmaf(sg[j], Whh[(size_t)g * 256 + 128 + j], a);
        d_S2[f * G4 + g] = a;
    } else {
        float a = 0.f;
        #pragma unroll
        for (int f = 0; f < FEW; f++) a += d_SG[f * 128 + t];
        d_MS[t] = a * 0.2f;
    }
}

// ---------------- gather q; q16; hl16 = -q (step-0 trick, re-init every call) ----------------
__global__ void k_gather(const int* __restrict__ qp, const float* __restrict__ emb) {
    int row = blockIdx.x * 8 + (threadIdx.x >> 5);
    int lane = threadIdx.x & 31;
    int idx = qp[row];
    float4 v = *(const float4*)(emb + (size_t)idx * 128 + lane * 4);
    *(float4*)(d_q + (size_t)row * 128 + lane * 4) = v;
    *(__half2*)(d_q16  + (size_t)row * 128 + lane * 4)     = __floats2half2_rn(v.x, v.y);
    *(__half2*)(d_q16  + (size_t)row * 128 + lane * 4 + 2) = __floats2half2_rn(v.z, v.w);
    *(__half2*)(d_hl16 + (size_t)row * 128 + lane * 4)     = __floats2half2_rn(-v.x, -v.y);
    *(__half2*)(d_hl16 + (size_t)row * 128 + lane * 4 + 2) = __floats2half2_rn(-v.z, -v.w);
}

// ---------------- Gbuf precompute: 128 rows/block, loops 8 N tiles ----------------
__global__ void __launch_bounds__(256, 2) k_gbuf(const __half* __restrict__ A,
                                                 const __half* __restrict__ B) {
    extern __shared__ char smraw[];
    __half* As   = (__half*)smraw;
    __half* Bs   = (__half*)(smraw + GB_OFF_BS);
    float* sBias = (float*)(smraw + GB_OFF_BIAS);

    int by = blockIdx.x;
    int tid = threadIdx.x, lane = tid & 31, warp = tid >> 5;
    int g = lane >> 2, tg = lane & 3;
    int wm = warp >> 2, wn = warp & 3;

    const __half* Ag = A + (size_t)by * 128 * 128;
    #pragma unroll
    for (int it = 0; it < 8; it++) {
        int i = tid + it * 256; int r = i >> 4, c8 = (i & 15) << 3;
        *(uint4*)(As + r * SST + c8) = *(const uint4*)(Ag + r * 128 + c8);
    }
    for (int i = tid; i < G4; i += 256) sBias[i] = d_bsum[i];

    for (int nn = 0; nn < 8; nn++) {
        __syncthreads();
        const __half* Bg = B + (size_t)nn * 128 * 128;
        #pragma unroll
        for (int it = 0; it < 8; it++) {
            int i = tid + it * 256; int r = i >> 4, c8 = (i & 15) << 3;
            *(uint4*)(Bs + r * SST + c8) = *(const uint4*)(Bg + r * 128 + c8);
        }
        __syncthreads();

        float acc[4][4][4];
        #pragma unroll
        for (int mi = 0; mi < 4; mi++)
            #pragma unroll
            for (int ni = 0; ni < 4; ni++)
                #pragma unroll
                for (int r = 0; r < 4; r++) acc[mi][ni][r] = 0.f;

        #pragma unroll
        for (int kk = 0; kk < 8; kk++) {
            int c0 = kk * 16 + 2 * tg;
            unsigned a[4][4];
            #pragma unroll
            for (int mi = 0; mi < 4; mi++) {
                const __half* p = As + (wm * 64 + mi * 16 + g) * SST + c0;
                a[mi][0] = *(const unsigned*)(p);
                a[mi][1] = *(const unsigned*)(p + 8 * SST);
                a[mi][2] = *(const unsigned*)(p + 8);
                a[mi][3] = *(const unsigned*)(p + 8 * SST + 8);
            }
            #pragma unroll
            for (int ni = 0; ni < 4; ni++) {
                const __half* p = Bs + (wn * 32 + ni * 8 + g) * SST + c0;
                unsigned b0 = *(const unsigned*)(p);
                unsigned b1 = *(const unsigned*)(p + 8);
                #pragma unroll
                for (int mi = 0; mi < 4; mi++)
                    mma_f16(acc[mi][ni], a[mi], b0, b1);
            }
        }

        #pragma unroll
        for (int mi = 0; mi < 4; mi++) {
            #pragma unroll
            for (int ni = 0; ni < 4; ni++) {
                int rl0 = wm * 64 + mi * 16 + g;
                int cit = wn * 32 + ni * 8 + 2 * tg;
                int gcol = nn * 128 + cit;
                #pragma unroll
                for (int rr = 0; rr < 2; rr++) {
                    size_t row = (size_t)(by * 128 + rl0 + rr * 8);
                    float x0 = acc[mi][ni][rr * 2 + 0] + sBias[gcol];
                    float x1 = acc[mi][ni][rr * 2 + 1] + sBias[gcol + 1];
                    *(__half2*)(d_Gbuf + row * G4 + gcol) = __floats2half2_rn(x0, x1);
                }
            }
        }
    }
}

// ---------------- fused step: GEMM (64 rows x all gate cols) + LSTM in registers ----------------
// For each column-half h (cells j in [h*128, h*128+128)), tiles G=0..3 (i,f,g,o) are
// processed in order; the SAME thread owns the same (row, col) fragment in every tile,
// so the LSTM cell update happens entirely in registers. Gates stay fp32 (never stored).
__global__ void __launch_bounds__(256) k_step(const __half* __restrict__ A,
                                              int first, int hasattn, int last) {
    extern __shared__ char smraw[];
    __half* As = (__half*)smraw;                     // 64 x SST
    __half* Bs = (__half*)(smraw + ST_OFF_BS);       // 128 x SST
    float* sS2 = (float*)(smraw + ST_OFF_SS2);       // 5 x 1024
    float* sAt = (float*)(smraw + ST_OFF_SAT);       // 64 x 5

    int by = blockIdx.x;
    int tid = threadIdx.x, lane = tid & 31, warp = tid >> 5;
    int g = lane >> 2, tg = lane & 3;
    int wm = warp >> 2, wn = warp & 3;               // 2(M) x 4(N); warp tile 32 x 32

    const __half* Ag = A + (size_t)by * 64 * 128;
    #pragma unroll
    for (int it = 0; it < 4; it++) {
        int i = tid + it * 256; int r = i >> 4, c8 = (i & 15) << 3;
        *(uint4*)(As + r * SST + c8) = *(const uint4*)(Ag + r * 128 + c8);
    }
    if (hasattn) {
        for (int i = tid; i < FEW * G4; i += 256) sS2[i] = d_S2[i];
        for (int i = tid; i < 64 * FEW; i += 256) {
            int r = i / FEW, f = i - r * FEW;
            sAt[i] = d_attn[(size_t)(by * 64 + r) * 8 + f];
        }
    }

    int nh = last ? 1 : 2;
    for (int h = 0; h < nh; h++) {
        float si[2][4][4];     // sigma(i)
        float cv[2][4][4];     // sigma(f)*c_prev, then c_new

        #pragma unroll
        for (int G = 0; G < 4; G++) {
            int nn = G * 2 + h;
            __syncthreads();                         // prior MMA/loads done with Bs, As ready
            const __half* Bg = d_W116 + (size_t)nn * 128 * 128;
            #pragma unroll
            for (int it = 0; it < 8; it++) {
                int i = tid + it * 256; int r = i >> 4, c8 = (i & 15) << 3;
                *(uint4*)(Bs + r * SST + c8) = *(const uint4*)(Bg + r * 128 + c8);
            }
            __syncthreads();

            float acc[2][4][4];
            #pragma unroll
            for (int mi = 0; mi < 2; mi++)
                #pragma unroll
                for (int ni = 0; ni < 4; ni++)
                    #pragma unroll
                    for (int r = 0; r < 4; r++) acc[mi][ni][r] = 0.f;

            #pragma unroll
            for (int kk = 0; kk < 8; kk++) {
                int c0 = kk * 16 + 2 * tg;
                unsigned a[2][4];
                #pragma unroll
                for (int mi = 0; mi < 2; mi++) {
                    const __half* p = As + (wm * 32 + mi * 16 + g) * SST + c0;
                    a[mi][0] = *(const unsigned*)(p);
                    a[mi][1] = *(const unsigned*)(p + 8 * SST);
                    a[mi][2] = *(const unsigned*)(p + 8);
                    a[mi][3] = *(const unsigned*)(p + 8 * SST + 8);
                }
                #pragma unroll
                for (int ni = 0; ni < 4; ni++) {
                    const __half* p = Bs + (wn * 32 + ni * 8 + g) * SST + c0;
                    unsigned b0 = *(const unsigned*)(p);
                    unsigned b1 = *(const unsigned*)(p + 8);
                    #pragma unroll
                    for (int mi = 0; mi < 2; mi++)
                        mma_f16(acc[mi][ni], a[mi], b0, b1);
                }
            }

            // epilogue for gate G: fp32 register LSTM state machine
            #pragma unroll
            for (int mi = 0; mi < 2; mi++) {
                #pragma unroll
                for (int ni = 0; ni < 4; ni++) {
                    #pragma unroll
                    for (int rr = 0; rr < 2; rr++) {
                        int rl = wm * 32 + mi * 16 + g + rr * 8;
                        int col = wn * 32 + ni * 8 + 2 * tg;
                        size_t row = (size_t)(by * 64 + rl);
                        int gcol = G * 256 + h * 128 + col;
                        __half2 gb2 = *(const __half2*)(d_Gbuf + row * G4 + gcol);
                        float2 gf = __half22float2(gb2);
                        float x0 = acc[mi][ni][rr * 2 + 0] + gf.x;
                        float x1 = acc[mi][ni][rr * 2 + 1] + gf.y;
                        if (hasattn) {
                            #pragma unroll
                            for (int f = 0; f < FEW; f++) {
                                float av = sAt[rl * FEW + f];
                                x0 = fmaf(av, sS2[f * G4 + gcol], x0);
                                x1 = fmaf(av, sS2[f * G4 + gcol + 1], x1);
                            }
                        }
                        int i0 = rr * 2, i1 = rr * 2 + 1;
                        if (G == 0) {                        // i gate
                            si[mi][ni][i0] = sigf(x0);
                            si[mi][ni][i1] = sigf(x1);
                        } else if (G == 1) {                 // f gate
                            float2 cp = make_float2(0.f, 0.f);
                            if (!first)
                                cp = *(const float2*)(d_c + row * 256 + h * 128 + col);
                            cv[mi][ni][i0] = sigf(x0) * cp.x;
                            cv[mi][ni][i1] = sigf(x1) * cp.y;
                        } else if (G == 2) {                 // g gate -> c_new
                            float c0 = fmaf(si[mi][ni][i0], tanhf(x0), cv[mi][ni][i0]);
                            float c1 = fmaf(si[mi][ni][i1], tanhf(x1), cv[mi][ni][i1]);
                            cv[mi][ni][i0] = c0; cv[mi][ni][i1] = c1;
                            if (!last)
                                *(float2*)(d_c + row * 256 + h * 128 + col) = make_float2(c0, c1);
                        } else {                             // o gate -> hl
                            if (h == 0) {
                                float hl0 = sigf(x0) * tanhf(cv[mi][ni][i0]);
                                float hl1 = sigf(x1) * tanhf(cv[mi][ni][i1]);
                                if (!last)
                                    *(__half2*)(d_hl16 + row * 128 + col) = __floats2half2_rn(hl0, hl1);
                                else
                                    *(float2*)(d_hl + row * 128 + col) = make_float2(hl0, hl1);
                            }
                        }
                    }
                }
            }
        }
    }
}

// ---------------- attention logits + softmax (per step) ----------------
__global__ void __launch_bounds__(256) k_attn() {
    __shared__ float sSg[FEW * 128];
    for (int i = threadIdx.x; i < FEW * 128; i += 256) sSg[i] = d_SG[i];
    __syncthreads();
    int row = blockIdx.x * 8 + (threadIdx.x >> 5);
    int lane = threadIdx.x & 31;
    float part[FEW] = {0.f, 0.f, 0.f, 0.f, 0.f};
    #pragma unroll
    for (int k = 0; k < 4; k++) {
        int j = lane + 32 * k;
        float hq = __half2float(d_q16[(size_t)row * 128 + j]) +
                   __half2float(d_hl16[(size_t)row * 128 + j]);
        #pragma unroll
        for (int f = 0; f < FEW; f++) part[f] = fmaf(hq, sSg[f * 128 + j], part[f]);
    }
    #pragma unroll
    for (int o = 16; o; o >>= 1)
        #pragma unroll
        for (int f = 0; f < FEW; f++) part[f] += __shfl_xor_sync(0xffffffffu, part[f], o);
    if (lane == 0) {
        float m = part[0];
        #pragma unroll
        for (int f = 1; f < FEW; f++) m = fmaxf(m, part[f]);
        float e[FEW], ss = 0.f;
        #pragma unroll
        for (int f = 0; f < FEW; f++) { e[f] = expf(part[f] - m); ss += e[f]; }
        float inv = 1.f / ss;
        #pragma unroll
        for (int f = 0; f < FEW; f++) d_attn[(size_t)row * 8 + f] = e[f] * inv;
    }
}

// ---------------- final: out[b] = mean(hq[2b], hq[2b+1]) . mean_support ----------------
__global__ void k_final(float* __restrict__ out) {
    __shared__ float ms[128];
    int t = threadIdx.x;
    if (t < 128) ms[t] = d_MS[t];
    __syncthreads();
    int b = blockIdx.x * 8 + (t >> 5);
    int lane = t & 31;
    const float* q0 = d_q  + (size_t)b * 256;
    const float* h0 = d_hl + (size_t)b * 256;
    int j = lane * 4;
    float4 qa = *(const float4*)(q0 + j);
    float4 qb = *(const float4*)(q0 + 128 + j);
    float4 ha = *(const float4*)(h0 + j);
    float4 hb = *(const float4*)(h0 + 128 + j);
    float4 m4 = *(const float4*)(ms + j);
    float p = 0.5f * ((qa.x + ha.x + qb.x + hb.x) * m4.x +
                      (qa.y + ha.y + qb.y + hb.y) * m4.y +
                      (qa.z + ha.z + qb.z + hb.z) * m4.z +
                      (qa.w + ha.w + qb.w + hb.w) * m4.w);
    #pragma unroll
    for (int o = 16; o; o >>= 1) p += __shfl_xor_sync(0xffffffffu, p, o);
    if (lane == 0) out[b] = p;
}

// ---------------- launcher ----------------
extern "C" void kernel_launch(void* const* d_in, const int* in_sizes, int n_in,
                              void* d_out, int out_size) {
    const int*   qp  = (const int*)d_in[0];
    const int*   sp  = (const int*)d_in[1];
    const float* emb = (const float*)d_in[2];
    const float* gW  = (const float*)d_in[3];
    const float* gb  = (const float*)d_in[4];
    const float* p1W = (const float*)d_in[5];
    const float* p1b = (const float*)d_in[6];
    const float* p2W = (const float*)d_in[7];
    const float* p2b = (const float*)d_in[8];
    const float* lng = (const float*)d_in[9];
    const float* lnb = (const float*)d_in[10];
    const float* Wih = (const float*)d_in[11];
    const float* Whh = (const float*)d_in[12];
    const float* bih = (const float*)d_in[13];
    const float* bhh = (const float*)d_in[14];
    float* out = (float*)d_out;

    static int attr_set = 0;
    if (!attr_set) {
        cudaFuncSetAttribute(k_gbuf, cudaFuncAttributeMaxDynamicSharedMemorySize, SMEM_GBUF);
        cudaFuncSetAttribute(k_step, cudaFuncAttributeMaxDynamicSharedMemorySize, SMEM_STEP);
        attr_set = 1;
    }

    k_wsum<<<512, 256>>>(Wih, Whh, bih, bhh);
    k_support<<<5, 256>>>(sp, emb, gW, gb, p1W, p1b, p2W, p2b, lng, lnb);
    k_s2mean<<<41, 128>>>(Whh);
    k_gather<<<NQ / 8, 256>>>(qp, emb);

    __half* pQ16; cudaGetSymbolAddress((void**)&pQ16, d_q16);
    __half* pHL;  cudaGetSymbolAddress((void**)&pHL,  d_hl16);
    __half* pWc;  cudaGetSymbolAddress((void**)&pWc,  d_Wc16);

    // Gbuf = q @ (Wih + W1).T + bsum   (fp16)
    k_gbuf<<<NQ / 128, 256, SMEM_GBUF>>>(pQ16, pWc);

    // step 0: A = -q (in hl16), c=0, no attn
    k_step<<<NQ / 64, 256, SMEM_STEP>>>(pHL, 1, 0, 0);
    k_attn<<<NQ / 8, 256>>>();
    // steps 1,2
    k_step<<<NQ / 64, 256, SMEM_STEP>>>(pHL, 0, 1, 0);
    k_attn<<<NQ / 8, 256>>>();
    k_step<<<NQ / 64, 256, SMEM_STEP>>>(pHL, 0, 1, 0);
    k_attn<<<NQ / 8, 256>>>();
    // step 3 (last): only h=0, writes fp32 d_hl, no c store
    k_step<<<NQ / 64, 256, SMEM_STEP>>>(pHL, 0, 1, 1);

    k_final<<<16384 / 8, 256>>>(out);
}

// round 10
// speedup vs baseline: 2.1365x; 2.1365x over previous
#include <cuda_runtime.h>
#include <cuda_fp16.h>
#include <math.h>

// ---------------- problem constants ----------------
#define NQ      32768      // BATCH*2 query rows
#define D       128
#define GW      512        // packed gate width: {i,f,g,o} x j<128 (j>=128 is dead code)
#define FEW     5
#define SST     136        // smem stride (halfs): conflict-free fragment banks

// k_gates smem (bytes): As 34816 | Bs 34816 | sS2 10240 | sAt 2560 | bias 2048
#define OFF_BS    34816
#define OFF_SS2   69632
#define OFF_SAT   79872
#define OFF_BIAS  82432
#define SMEM_GATES 84480

// ---------------- scratch (static device arrays; no allocation) ----------------
__device__ float  d_SG[FEW * D];                 // support_g (5 x 128)
__device__ float  d_S2[FEW * GW];                // SG @ W2.T, packed 512 cols
__device__ float  d_MS[D];                       // mean_support
__device__ float  d_q   [(size_t)NQ * D];        // gathered query embeddings (fp32)
__device__ __half d_q16 [(size_t)NQ * D];        // fp16 q
__device__ __half d_hl16[(size_t)NQ * D];        // hl fp16 (init -q; rewritten per step)
__device__ float  d_hl  [(size_t)NQ * D];        // fp32 hl (last step only)
__device__ __half d_Gbuf[(size_t)NQ * GW];       // packed G01 (fp16)
__device__ __half d_gates[(size_t)NQ * GW];      // packed per-step gates (fp16)
__device__ float  d_c   [(size_t)NQ * D];        // LSTM cell state, j<128 only (fp32)
__device__ float  d_attn[(size_t)NQ * 8];        // attention weights (5, padded 8)
__device__ __half d_Wc16[GW * D];                // packed Wih + W1 (fp16)
__device__ __half d_W116[GW * D];                // packed W1 (fp16)
__device__ float  d_bsum[GW];                    // packed b_ih + b_hh

__device__ __forceinline__ float sigf(float x) { return 1.0f / (1.0f + expf(-x)); }

__device__ __forceinline__ void mma_f16(float* c, const unsigned* a, unsigned b0, unsigned b1) {
    asm volatile(
        "mma.sync.aligned.m16n8k16.row.col.f32.f16.f16.f32 "
        "{%0,%1,%2,%3}, {%4,%5,%6,%7}, {%8,%9}, {%0,%1,%2,%3};"
        : "+f"(c[0]), "+f"(c[1]), "+f"(c[2]), "+f"(c[3])
        : "r"(a[0]), "r"(a[1]), "r"(a[2]), "r"(a[3]), "r"(b0), "r"(b1));
}

// ---------------- prep: packed fp16 weights / bsum ----------------
// packed row pr in [0,512): gate = pr>>7, j = pr&127 ; original row = gate*256 + j
__global__ void k_wsum(const float* __restrict__ Wih, const float* __restrict__ Whh,
                       const float* __restrict__ bih, const float* __restrict__ bhh) {
    int idx = blockIdx.x * 256 + threadIdx.x;           // 512*128 = 65536
    int pr = idx >> 7, k = idx & 127;
    int orig = ((pr >> 7) << 8) + (pr & 127);           // gate*256 + j
    float w1 = Whh[(size_t)orig * 256 + k];
    d_Wc16[idx] = __float2half_rn(Wih[(size_t)orig * 128 + k] + w1);
    d_W116[idx] = __float2half_rn(w1);
    if (idx < GW) {
        int o2 = ((idx >> 7) << 8) + (idx & 127);
        d_bsum[idx] = bih[o2] + bhh[o2];
    }
}

// ---------------- support path: GCN (linear!) + MLP + LayerNorm ----------------
__global__ void k_support(const int* __restrict__ sp, const float* __restrict__ emb,
                          const float* __restrict__ gW, const float* __restrict__ gb,
                          const float* __restrict__ p1W, const float* __restrict__ p1b,
                          const float* __restrict__ p2W, const float* __restrict__ p2b,
                          const float* __restrict__ lng, const float* __restrict__ lnb) {
    __shared__ float cs[256], s[128], h1[256], x[128], stat[2];
    int f = blockIdx.x, t = threadIdx.x;
    int side = t >> 7, col = t & 127;
    const int* pf = sp + f * 400;
    float acc = 0.f;
    #pragma unroll 4
    for (int n = 0; n < 200; n++) {
        int idx = pf[n * 2 + side];
        acc += emb[(size_t)idx * 128 + col];
    }
    cs[t] = acc;
    __syncthreads();
    if (t < 128) {
        float a = 200.f * gb[t];
        #pragma unroll 4
        for (int k = 0; k < 256; k++) a = fmaf(cs[k], gW[t * 256 + k], a);
        s[t] = tanhf(a * 0.2f);
    }
    __syncthreads();
    {
        float a = p1b[t];
        #pragma unroll 4
        for (int j = 0; j < 128; j++) a = fmaf(s[j], p1W[t * 128 + j], a);
        h1[t] = fmaxf(a, 0.f);
    }
    __syncthreads();
    if (t < 128) {
        float a = p2b[t];
        #pragma unroll 4
        for (int k = 0; k < 256; k++) a = fmaf(h1[k], p2W[t * 256 + k], a);
        x[t] = a + s[t];
    }
    __syncthreads();
    if (t == 0) {
        float mu = 0.f;
        for (int j = 0; j < 128; j++) mu += x[j];
        mu *= (1.f / 128.f);
        float v = 0.f;
        for (int j = 0; j < 128; j++) { float dd = x[j] - mu; v += dd * dd; }
        v *= (1.f / 128.f);
        stat[0] = mu; stat[1] = rsqrtf(v + 1e-5f);
    }
    __syncthreads();
    if (t < 128) d_SG[f * 128 + t] = lng[t] * (x[t] - stat[0]) * stat[1] + lnb[t];
}

// ---------------- S2 (packed 512 cols) + mean_support ----------------
__global__ void k_s2mean(const float* __restrict__ Whh) {
    __shared__ float sg[128];
    int b = blockIdx.x, t = threadIdx.x;
    if (b < 20) {
        int f = b >> 2, gbk = b & 3;
        sg[t] = d_SG[f * 128 + t];
        __syncthreads();
        int pc = gbk * 128 + t;                       // packed col
        int orig = ((pc >> 7) << 8) + (pc & 127);
        float a = 0.f;
        #pragma unroll 4
        for (int j = 0; j < 128; j++) a = fmaf(sg[j], Whh[(size_t)orig * 256 + 128 + j], a);
        d_S2[f * GW + pc] = a;
    } else {
        float a = 0.f;
        #pragma unroll
        for (int f = 0; f < FEW; f++) a += d_SG[f * 128 + t];
        d_MS[t] = a * 0.2f;
    }
}

// ---------------- gather q; q16; hl16 = -q (step-0 trick, re-init every call) ----------------
__global__ void k_gather(const int* __restrict__ qp, const float* __restrict__ emb) {
    int row = blockIdx.x * 8 + (threadIdx.x >> 5);
    int lane = threadIdx.x & 31;
    int idx = qp[row];
    float4 v = *(const float4*)(emb + (size_t)idx * 128 + lane * 4);
    *(float4*)(d_q + (size_t)row * 128 + lane * 4) = v;
    *(__half2*)(d_q16  + (size_t)row * 128 + lane * 4)     = __floats2half2_rn(v.x, v.y);
    *(__half2*)(d_q16  + (size_t)row * 128 + lane * 4 + 2) = __floats2half2_rn(v.z, v.w);
    *(__half2*)(d_hl16 + (size_t)row * 128 + lane * 4)     = __floats2half2_rn(-v.x, -v.y);
    *(__half2*)(d_hl16 + (size_t)row * 128 + lane * 4 + 2) = __floats2half2_rn(-v.z, -v.w);
}

// ---------------- N-looped fp16 GEMM: 128 rows/block, 4 packed N tiles of 128 ----------------
// mode 0: Gbuf  = A@B.T + bsum          (A=q16,  B=Wc16)
// mode 1: gates = A@B.T + Gbuf          (A=-q16 in hl16, B=W116)   [step 0]
// mode 2: gates = A@B.T + Gbuf + attn@S2
__global__ void __launch_bounds__(256, 2) k_gates(const __half* __restrict__ A,
                                                  const __half* __restrict__ B,
                                                  int mode) {
    extern __shared__ char smraw[];
    __half* As  = (__half*)smraw;
    __half* Bs  = (__half*)(smraw + OFF_BS);
    float* sS2  = (float*)(smraw + OFF_SS2);
    float* sAt  = (float*)(smraw + OFF_SAT);
    float* sBias= (float*)(smraw + OFF_BIAS);

    int by = blockIdx.x;
    int tid = threadIdx.x, lane = tid & 31, warp = tid >> 5;
    int g = lane >> 2, tg = lane & 3;
    int wm = warp >> 2, wn = warp & 3;          // 2(M) x 4(N); warp tile 64 x 32

    const __half* Ag = A + (size_t)by * 128 * 128;
    #pragma unroll
    for (int it = 0; it < 8; it++) {
        int i = tid + it * 256; int r = i >> 4, c8 = (i & 15) << 3;
        *(uint4*)(As + r * SST + c8) = *(const uint4*)(Ag + r * 128 + c8);
    }
    if (mode == 2) {
        for (int i = tid; i < FEW * GW; i += 256) sS2[i] = d_S2[i];
        for (int i = tid; i < 128 * FEW; i += 256) {
            int r = i / FEW, f = i - r * FEW;
            sAt[i] = d_attn[(size_t)(by * 128 + r) * 8 + f];
        }
    }
    if (mode == 0) {
        for (int i = tid; i < GW; i += 256) sBias[i] = d_bsum[i];
    }

    for (int nn = 0; nn < 4; nn++) {
        __syncthreads();                         // prev MMA done with Bs; As/extras ready
        const __half* Bg = B + (size_t)nn * 128 * 128;
        #pragma unroll
        for (int it = 0; it < 8; it++) {
            int i = tid + it * 256; int r = i >> 4, c8 = (i & 15) << 3;
            *(uint4*)(Bs + r * SST + c8) = *(const uint4*)(Bg + r * 128 + c8);
        }
        __syncthreads();

        float acc[4][4][4];
        #pragma unroll
        for (int mi = 0; mi < 4; mi++)
            #pragma unroll
            for (int ni = 0; ni < 4; ni++)
                #pragma unroll
                for (int r = 0; r < 4; r++) acc[mi][ni][r] = 0.f;

        #pragma unroll
        for (int kk = 0; kk < 8; kk++) {
            int c0 = kk * 16 + 2 * tg;
            unsigned a[4][4];
            #pragma unroll
            for (int mi = 0; mi < 4; mi++) {
                const __half* p = As + (wm * 64 + mi * 16 + g) * SST + c0;
                a[mi][0] = *(const unsigned*)(p);
                a[mi][1] = *(const unsigned*)(p + 8 * SST);
                a[mi][2] = *(const unsigned*)(p + 8);
                a[mi][3] = *(const unsigned*)(p + 8 * SST + 8);
            }
            #pragma unroll
            for (int ni = 0; ni < 4; ni++) {
                const __half* p = Bs + (wn * 32 + ni * 8 + g) * SST + c0;
                unsigned b0 = *(const unsigned*)(p);
                unsigned b1 = *(const unsigned*)(p + 8);
                #pragma unroll
                for (int mi = 0; mi < 4; mi++)
                    mma_f16(acc[mi][ni], a[mi], b0, b1);
            }
        }

        // epilogue for this N tile
        #pragma unroll
        for (int mi = 0; mi < 4; mi++) {
            #pragma unroll
            for (int ni = 0; ni < 4; ni++) {
                int rl0 = wm * 64 + mi * 16 + g;
                int cit = wn * 32 + ni * 8 + 2 * tg;
                int gcol = nn * 128 + cit;
                #pragma unroll
                for (int rr = 0; rr < 2; rr++) {
                    int rl = rl0 + rr * 8;
                    size_t row = (size_t)(by * 128 + rl);
                    float x0 = acc[mi][ni][rr * 2 + 0];
                    float x1 = acc[mi][ni][rr * 2 + 1];
                    if (mode == 0) {
                        x0 += sBias[gcol]; x1 += sBias[gcol + 1];
                        *(__half2*)(d_Gbuf + row * GW + gcol) = __floats2half2_rn(x0, x1);
                    } else {
                        float2 gf = __half22float2(*(const __half2*)(d_Gbuf + row * GW + gcol));
                        x0 += gf.x; x1 += gf.y;
                        if (mode == 2) {
                            #pragma unroll
                            for (int f = 0; f < FEW; f++) {
                                float av = sAt[rl * FEW + f];
                                x0 = fmaf(av, sS2[f * GW + gcol], x0);
                                x1 = fmaf(av, sS2[f * GW + gcol + 1], x1);
                            }
                        }
                        *(__half2*)(d_gates + row * GW + gcol) = __floats2half2_rn(x0, x1);
                    }
                }
            }
        }
    }
}

// ---------------- elementwise LSTM update (j<128 only) + attention softmax ----------------
__global__ void __launch_bounds__(256) k_lstm(int first) {
    __shared__ float sSg[FEW * 128];
    for (int i = threadIdx.x; i < FEW * 128; i += 256) sSg[i] = d_SG[i];
    __syncthreads();
    int row = blockIdx.x * 8 + (threadIdx.x >> 5);
    int lane = threadIdx.x & 31;
    const __half* gr = d_gates + (size_t)row * GW;
    float part[FEW] = {0.f, 0.f, 0.f, 0.f, 0.f};
    #pragma unroll
    for (int k = 0; k < 4; k++) {
        int j = lane + 32 * k;
        float gi = __half2float(gr[j]);
        float gf = __half2float(gr[128 + j]);
        float gg = __half2float(gr[256 + j]);
        float go = __half2float(gr[384 + j]);
        float co = first ? 0.f : d_c[(size_t)row * 128 + j];
        float cn = fmaf(sigf(gf), co, sigf(gi) * tanhf(gg));
        d_c[(size_t)row * 128 + j] = cn;
        float hl = sigf(go) * tanhf(cn);
        float hq = __half2float(d_q16[(size_t)row * 128 + j]) + hl;
        d_hl16[(size_t)row * 128 + j] = __float2half_rn(hl);
        #pragma unroll
        for (int f = 0; f < FEW; f++) part[f] = fmaf(hq, sSg[f * 128 + j], part[f]);
    }
    #pragma unroll
    for (int o = 16; o; o >>= 1)
        #pragma unroll
        for (int f = 0; f < FEW; f++) part[f] += __shfl_xor_sync(0xffffffffu, part[f], o);
    if (lane == 0) {
        float m = part[0];
        #pragma unroll
        for (int f = 1; f < FEW; f++) m = fmaxf(m, part[f]);
        float e[FEW], ss = 0.f;
        #pragma unroll
        for (int f = 0; f < FEW; f++) { e[f] = expf(part[f] - m); ss += e[f]; }
        float inv = 1.f / ss;
        #pragma unroll
        for (int f = 0; f < FEW; f++) d_attn[(size_t)row * 8 + f] = e[f] * inv;
    }
}

// last step: no attention, no c store; hl written fp32 for k_final
__global__ void __launch_bounds__(256) k_lstm_last() {
    int row = blockIdx.x * 8 + (threadIdx.x >> 5);
    int lane = threadIdx.x & 31;
    const __half* gr = d_gates + (size_t)row * GW;
    #pragma unroll
    for (int k = 0; k < 4; k++) {
        int j = lane + 32 * k;
        float gi = __half2float(gr[j]);
        float gf = __half2float(gr[128 + j]);
        float gg = __half2float(gr[256 + j]);
        float go = __half2float(gr[384 + j]);
        float co = d_c[(size_t)row * 128 + j];
        float cn = fmaf(sigf(gf), co, sigf(gi) * tanhf(gg));
        float hl = sigf(go) * tanhf(cn);
        d_hl[(size_t)row * 128 + j] = hl;
    }
}

// ---------------- final: out[b] = mean(hq[2b], hq[2b+1]) . mean_support ----------------
__global__ void k_final(float* __restrict__ out) {
    __shared__ float ms[128];
    int t = threadIdx.x;
    if (t < 128) ms[t] = d_MS[t];
    __syncthreads();
    int b = blockIdx.x * 8 + (t >> 5);
    int lane = t & 31;
    const float* q0 = d_q  + (size_t)b * 256;
    const float* h0 = d_hl + (size_t)b * 256;
    int j = lane * 4;
    float4 qa = *(const float4*)(q0 + j);
    float4 qb = *(const float4*)(q0 + 128 + j);
    float4 ha = *(const float4*)(h0 + j);
    float4 hb = *(const float4*)(h0 + 128 + j);
    float4 m4 = *(const float4*)(ms + j);
    float p = 0.5f * ((qa.x + ha.x + qb.x + hb.x) * m4.x +
                      (qa.y + ha.y + qb.y + hb.y) * m4.y +
                      (qa.z + ha.z + qb.z + hb.z) * m4.z +
                      (qa.w + ha.w + qb.w + hb.w) * m4.w);
    #pragma unroll
    for (int o = 16; o; o >>= 1) p += __shfl_xor_sync(0xffffffffu, p, o);
    if (lane == 0) out[b] = p;
}

// ---------------- launcher ----------------
extern "C" void kernel_launch(void* const* d_in, const int* in_sizes, int n_in,
                              void* d_out, int out_size) {
    const int*   qp  = (const int*)d_in[0];
    const int*   sp  = (const int*)d_in[1];
    const float* emb = (const float*)d_in[2];
    const float* gW  = (const float*)d_in[3];
    const float* gb  = (const float*)d_in[4];
    const float* p1W = (const float*)d_in[5];
    const float* p1b = (const float*)d_in[6];
    const float* p2W = (const float*)d_in[7];
    const float* p2b = (const float*)d_in[8];
    const float* lng = (const float*)d_in[9];
    const float* lnb = (const float*)d_in[10];
    const float* Wih = (const float*)d_in[11];
    const float* Whh = (const float*)d_in[12];
    const float* bih = (const float*)d_in[13];
    const float* bhh = (const float*)d_in[14];
    float* out = (float*)d_out;

    static int attr_set = 0;
    if (!attr_set) {
        cudaFuncSetAttribute(k_gates, cudaFuncAttributeMaxDynamicSharedMemorySize, SMEM_GATES);
        attr_set = 1;
    }

    k_wsum<<<256, 256>>>(Wih, Whh, bih, bhh);
    k_support<<<5, 256>>>(sp, emb, gW, gb, p1W, p1b, p2W, p2b, lng, lnb);
    k_s2mean<<<21, 128>>>(Whh);
    k_gather<<<NQ / 8, 256>>>(qp, emb);

    __half* pQ16; cudaGetSymbolAddress((void**)&pQ16, d_q16);
    __half* pHL;  cudaGetSymbolAddress((void**)&pHL,  d_hl16);
    __half* pWc;  cudaGetSymbolAddress((void**)&pWc,  d_Wc16);
    __half* pW1;  cudaGetSymbolAddress((void**)&pW1,  d_W116);

    // Gbuf (packed 512) = q @ (Wih + W1).T + bsum
    k_gates<<<NQ / 128, 256, SMEM_GATES>>>(pQ16, pWc, 0);

    // step 0: gates = Gbuf + (-q)@W1.T  (hl16 holds -q)
    k_gates<<<NQ / 128, 256, SMEM_GATES>>>(pHL, pW1, 1);
    k_lstm<<<NQ / 8, 256>>>(1);

    // steps 1,2: gates = Gbuf + hl@W1.T + attn@S2
    for (int t = 0; t < 2; t++) {
        k_gates<<<NQ / 128, 256, SMEM_GATES>>>(pHL, pW1, 2);
        k_lstm<<<NQ / 8, 256>>>(0);
    }

    // step 3 (last)
    k_gates<<<NQ / 128, 256, SMEM_GATES>>>(pHL, pW1, 2);
    k_lstm_last<<<NQ / 8, 256>>>();

    k_final<<<16384 / 8, 256>>>(out);
}

// round 11
// speedup vs baseline: 2.6518x; 1.2412x over previous
#include <cuda_runtime.h>
#include <cuda_fp16.h>
#include <math.h>

// ---------------- problem constants ----------------
#define NQ      32768      // BATCH*2 query rows
#define D       128
#define GW      512        // packed gate width: {i,f,g,o} x j<128 (j>=128 is dead)
#define FEW     5
#define SSTA    264        // A smem stride (halfs), K=256 + pad: banks (4g+tg)%32 CF
#define SSTB    136        // B smem stride (halfs), K=128 tile: conflict-free

// k_gates smem layout (bytes)
#define OFF_BS    67584                 // As: 128*264*2
#define OFF_SS2H  102400                // Bs: 128*136*2
#define OFF_SAT   107520                // sS2h: 5*512*2
#define OFF_BIAS  110080                // sAt: 128*5*4
#define SMEM_GATES 112128               // sBias: 512*4

// ---------------- scratch (static device arrays; no allocation) ----------------
__device__ float  d_SG[FEW * D];                 // support_g (5 x 128)
__device__ float  d_S2[FEW * GW];                // SG @ W2.T, packed 512 cols
__device__ float  d_MS[D];                       // mean_support
__device__ float  d_q   [(size_t)NQ * D];        // gathered query embeddings (fp32)
__device__ __half d_qhl [(size_t)NQ * 256];      // cols 0-127: q16 ; 128-255: hl16 (init -q)
__device__ float  d_hl  [(size_t)NQ * D];        // fp32 hl (last step only)
__device__ __half d_gates[(size_t)NQ * GW];      // packed per-step gates (fp16)
__device__ float  d_c   [(size_t)NQ * D];        // LSTM cell state, j<128 (fp32)
__device__ float  d_attn[(size_t)NQ * 8];        // attention weights (5, padded 8)
__device__ __half d_Wbig[GW * 256];              // [Wih+W1 | W1] packed 512x256 (fp16)
__device__ float  d_bsum[GW];                    // packed b_ih + b_hh

__device__ __forceinline__ float sigf(float x) {
    return __fdividef(1.0f, 1.0f + __expf(-x));
}
__device__ __forceinline__ float tanhfast(float x) {
    return __fdividef(2.0f, 1.0f + __expf(-2.0f * x)) - 1.0f;
}

__device__ __forceinline__ void mma_f16(float* c, const unsigned* a, unsigned b0, unsigned b1) {
    asm volatile(
        "mma.sync.aligned.m16n8k16.row.col.f32.f16.f16.f32 "
        "{%0,%1,%2,%3}, {%4,%5,%6,%7}, {%8,%9}, {%0,%1,%2,%3};"
        : "+f"(c[0]), "+f"(c[1]), "+f"(c[2]), "+f"(c[3])
        : "r"(a[0]), "r"(a[1]), "r"(a[2]), "r"(a[3]), "r"(b0), "r"(b1));
}

// ---------------- prep: packed fp16 Wbig = [Wih + W1 | W1] / bsum ----------------
// packed row pr in [0,512): gate = pr>>7, j = pr&127 ; original row = gate*256 + j
__global__ void k_wsum(const float* __restrict__ Wih, const float* __restrict__ Whh,
                       const float* __restrict__ bih, const float* __restrict__ bhh) {
    int idx = blockIdx.x * 256 + threadIdx.x;           // 512*256 = 131072
    int pr = idx >> 8, k = idx & 255;
    int orig = ((pr >> 7) << 8) + (pr & 127);           // gate*256 + j
    float val;
    if (k < 128) val = Wih[(size_t)orig * 128 + k] + Whh[(size_t)orig * 256 + k];
    else         val = Whh[(size_t)orig * 256 + (k - 128)];
    d_Wbig[idx] = __float2half_rn(val);
    if (idx < GW) {
        int o2 = ((idx >> 7) << 8) + (idx & 127);
        d_bsum[idx] = bih[o2] + bhh[o2];
    }
}

// ---------------- support path: GCN (linear!) + MLP + LayerNorm ----------------
__global__ void k_support(const int* __restrict__ sp, const float* __restrict__ emb,
                          const float* __restrict__ gW, const float* __restrict__ gb,
                          const float* __restrict__ p1W, const float* __restrict__ p1b,
                          const float* __restrict__ p2W, const float* __restrict__ p2b,
                          const float* __restrict__ lng, const float* __restrict__ lnb) {
    __shared__ float cs[256], s[128], h1[256], x[128], stat[2];
    int f = blockIdx.x, t = threadIdx.x;
    int side = t >> 7, col = t & 127;
    const int* pf = sp + f * 400;
    float acc = 0.f;
    #pragma unroll 4
    for (int n = 0; n < 200; n++) {
        int idx = pf[n * 2 + side];
        acc += emb[(size_t)idx * 128 + col];
    }
    cs[t] = acc;
    __syncthreads();
    if (t < 128) {
        float a = 200.f * gb[t];
        #pragma unroll 4
        for (int k = 0; k < 256; k++) a = fmaf(cs[k], gW[t * 256 + k], a);
        s[t] = tanhf(a * 0.2f);
    }
    __syncthreads();
    {
        float a = p1b[t];
        #pragma unroll 4
        for (int j = 0; j < 128; j++) a = fmaf(s[j], p1W[t * 128 + j], a);
        h1[t] = fmaxf(a, 0.f);
    }
    __syncthreads();
    if (t < 128) {
        float a = p2b[t];
        #pragma unroll 4
        for (int k = 0; k < 256; k++) a = fmaf(h1[k], p2W[t * 256 + k], a);
        x[t] = a + s[t];
    }
    __syncthreads();
    if (t == 0) {
        float mu = 0.f;
        for (int j = 0; j < 128; j++) mu += x[j];
        mu *= (1.f / 128.f);
        float v = 0.f;
        for (int j = 0; j < 128; j++) { float dd = x[j] - mu; v += dd * dd; }
        v *= (1.f / 128.f);
        stat[0] = mu; stat[1] = rsqrtf(v + 1e-5f);
    }
    __syncthreads();
    if (t < 128) d_SG[f * 128 + t] = lng[t] * (x[t] - stat[0]) * stat[1] + lnb[t];
}

// ---------------- S2 (packed 512 cols) + mean_support ----------------
__global__ void k_s2mean(const float* __restrict__ Whh) {
    __shared__ float sg[128];
    int b = blockIdx.x, t = threadIdx.x;
    if (b < 20) {
        int f = b >> 2, gbk = b & 3;
        sg[t] = d_SG[f * 128 + t];
        __syncthreads();
        int pc = gbk * 128 + t;
        int orig = ((pc >> 7) << 8) + (pc & 127);
        float a = 0.f;
        #pragma unroll 4
        for (int j = 0; j < 128; j++) a = fmaf(sg[j], Whh[(size_t)orig * 256 + 128 + j], a);
        d_S2[f * GW + pc] = a;
    } else {
        float a = 0.f;
        #pragma unroll
        for (int f = 0; f < FEW; f++) a += d_SG[f * 128 + t];
        d_MS[t] = a * 0.2f;
    }
}

// ---------------- gather: q fp32, qhl = [q16 | -q16] (step-0 trick) ----------------
__global__ void k_gather(const int* __restrict__ qp, const float* __restrict__ emb) {
    int row = blockIdx.x * 8 + (threadIdx.x >> 5);
    int lane = threadIdx.x & 31;
    int idx = qp[row];
    float4 v = *(const float4*)(emb + (size_t)idx * 128 + lane * 4);
    *(float4*)(d_q + (size_t)row * 128 + lane * 4) = v;
    __half* qr = d_qhl + (size_t)row * 256;
    *(__half2*)(qr + lane * 4)           = __floats2half2_rn(v.x, v.y);
    *(__half2*)(qr + lane * 4 + 2)       = __floats2half2_rn(v.z, v.w);
    *(__half2*)(qr + 128 + lane * 4)     = __floats2half2_rn(-v.x, -v.y);
    *(__half2*)(qr + 128 + lane * 4 + 2) = __floats2half2_rn(-v.z, -v.w);
}

// ---------------- step GEMM: gates = [q|hl] @ [Wc|W1].T + b (+ attn@S2) ----------------
// Block: 128 rows x all 512 packed gate cols (4 N tiles), K=256 in 2 halves.
__global__ void __launch_bounds__(256, 2) k_gates(int hasattn) {
    extern __shared__ char smraw[];
    __half* As   = (__half*)smraw;                       // 128 x 264
    __half* Bs   = (__half*)(smraw + OFF_BS);            // 128 x 136
    __half* sS2h = (__half*)(smraw + OFF_SS2H);          // 5 x 512
    float*  sAt  = (float*)(smraw + OFF_SAT);            // 128 x 5
    float*  sBias= (float*)(smraw + OFF_BIAS);           // 512

    int by = blockIdx.x;
    int tid = threadIdx.x, lane = tid & 31, warp = tid >> 5;
    int g = lane >> 2, tg = lane & 3;
    int wm = warp >> 2, wn = warp & 3;                   // 2(M) x 4(N); warp tile 64 x 32

    // A tile: 128 rows x 256 halfs (q | hl)
    const __half* Ag = d_qhl + (size_t)by * 128 * 256;
    #pragma unroll
    for (int it = 0; it < 16; it++) {
        int i = tid + it * 256; int r = i >> 5, c8 = (i & 31) << 3;
        *(uint4*)(As + r * SSTA + c8) = *(const uint4*)(Ag + r * 256 + c8);
    }
    if (hasattn) {
        for (int i = tid; i < FEW * GW; i += 256) sS2h[i] = __float2half_rn(d_S2[i]);
        for (int i = tid; i < 128 * FEW; i += 256) {
            int r = i / FEW, f = i - r * FEW;
            sAt[i] = d_attn[(size_t)(by * 128 + r) * 8 + f];
        }
    }
    for (int i = tid; i < GW; i += 256) sBias[i] = d_bsum[i];

    for (int nn = 0; nn < 4; nn++) {
        float acc[4][4][4];
        #pragma unroll
        for (int mi = 0; mi < 4; mi++)
            #pragma unroll
            for (int ni = 0; ni < 4; ni++)
                #pragma unroll
                for (int r = 0; r < 4; r++) acc[mi][ni][r] = 0.f;

        #pragma unroll
        for (int kh = 0; kh < 2; kh++) {
            __syncthreads();                             // prev users of Bs done; As ready
            const __half* Bg = d_Wbig + (size_t)(nn * 128) * 256 + kh * 128;
            #pragma unroll
            for (int it = 0; it < 8; it++) {
                int i = tid + it * 256; int r = i >> 4, c8 = (i & 15) << 3;
                *(uint4*)(Bs + r * SSTB + c8) = *(const uint4*)(Bg + r * 256 + c8);
            }
            __syncthreads();

            #pragma unroll
            for (int kk = 0; kk < 8; kk++) {
                int ca = kh * 128 + kk * 16 + 2 * tg;
                int cb = kk * 16 + 2 * tg;
                unsigned a[4][4];
                #pragma unroll
                for (int mi = 0; mi < 4; mi++) {
                    const __half* p = As + (wm * 64 + mi * 16 + g) * SSTA + ca;
                    a[mi][0] = *(const unsigned*)(p);
                    a[mi][1] = *(const unsigned*)(p + 8 * SSTA);
                    a[mi][2] = *(const unsigned*)(p + 8);
                    a[mi][3] = *(const unsigned*)(p + 8 * SSTA + 8);
                }
                #pragma unroll
                for (int ni = 0; ni < 4; ni++) {
                    const __half* p = Bs + (wn * 32 + ni * 8 + g) * SSTB + cb;
                    unsigned b0 = *(const unsigned*)(p);
                    unsigned b1 = *(const unsigned*)(p + 8);
                    #pragma unroll
                    for (int mi = 0; mi < 4; mi++)
                        mma_f16(acc[mi][ni], a[mi], b0, b1);
                }
            }
        }

        // epilogue for this N tile
        #pragma unroll
        for (int mi = 0; mi < 4; mi++) {
            #pragma unroll
            for (int ni = 0; ni < 4; ni++) {
                int rl0 = wm * 64 + mi * 16 + g;
                int cit = wn * 32 + ni * 8 + 2 * tg;
                int gcol = nn * 128 + cit;
                #pragma unroll
                for (int rr = 0; rr < 2; rr++) {
                    int rl = rl0 + rr * 8;
                    size_t row = (size_t)(by * 128 + rl);
                    float x0 = acc[mi][ni][rr * 2 + 0] + sBias[gcol];
                    float x1 = acc[mi][ni][rr * 2 + 1] + sBias[gcol + 1];
                    if (hasattn) {
                        #pragma unroll
                        for (int f = 0; f < FEW; f++) {
                            float av = sAt[rl * FEW + f];
                            x0 = fmaf(av, __half2float(sS2h[f * GW + gcol]), x0);
                            x1 = fmaf(av, __half2float(sS2h[f * GW + gcol + 1]), x1);
                        }
                    }
                    *(__half2*)(d_gates + row * GW + gcol) = __floats2half2_rn(x0, x1);
                }
            }
        }
    }
}

// ---------------- elementwise LSTM update (j<128) + attention softmax ----------------
__global__ void __launch_bounds__(256) k_lstm(int first) {
    __shared__ float sSg[FEW * 128];
    for (int i = threadIdx.x; i < FEW * 128; i += 256) sSg[i] = d_SG[i];
    __syncthreads();
    int row = blockIdx.x * 8 + (threadIdx.x >> 5);
    int lane = threadIdx.x & 31;
    const __half* gr = d_gates + (size_t)row * GW;
    __half* qr = d_qhl + (size_t)row * 256;
    float part[FEW] = {0.f, 0.f, 0.f, 0.f, 0.f};
    #pragma unroll
    for (int k = 0; k < 4; k++) {
        int j = lane + 32 * k;
        float gi = __half2float(gr[j]);
        float gf = __half2float(gr[128 + j]);
        float gg = __half2float(gr[256 + j]);
        float go = __half2float(gr[384 + j]);
        float co = first ? 0.f : d_c[(size_t)row * 128 + j];
        float cn = fmaf(sigf(gf), co, sigf(gi) * tanhfast(gg));
        d_c[(size_t)row * 128 + j] = cn;
        float hl = sigf(go) * tanhfast(cn);
        float hq = __half2float(qr[j]) + hl;
        qr[128 + j] = __float2half_rn(hl);
        #pragma unroll
        for (int f = 0; f < FEW; f++) part[f] = fmaf(hq, sSg[f * 128 + j], part[f]);
    }
    #pragma unroll
    for (int o = 16; o; o >>= 1)
        #pragma unroll
        for (int f = 0; f < FEW; f++) part[f] += __shfl_xor_sync(0xffffffffu, part[f], o);
    if (lane == 0) {
        float m = part[0];
        #pragma unroll
        for (int f = 1; f < FEW; f++) m = fmaxf(m, part[f]);
        float e[FEW], ss = 0.f;
        #pragma unroll
        for (int f = 0; f < FEW; f++) { e[f] = __expf(part[f] - m); ss += e[f]; }
        float inv = __fdividef(1.f, ss);
        #pragma unroll
        for (int f = 0; f < FEW; f++) d_attn[(size_t)row * 8 + f] = e[f] * inv;
    }
}

// last step: no attention, no c store; hl written fp32 for k_final
__global__ void __launch_bounds__(256) k_lstm_last() {
    int row = blockIdx.x * 8 + (threadIdx.x >> 5);
    int lane = threadIdx.x & 31;
    const __half* gr = d_gates + (size_t)row * GW;
    #pragma unroll
    for (int k = 0; k < 4; k++) {
        int j = lane + 32 * k;
        float gi = __half2float(gr[j]);
        float gf = __half2float(gr[128 + j]);
        float gg = __half2float(gr[256 + j]);
        float go = __half2float(gr[384 + j]);
        float co = d_c[(size_t)row * 128 + j];
        float cn = fmaf(sigf(gf), co, sigf(gi) * tanhfast(gg));
        float hl = sigf(go) * tanhfast(cn);
        d_hl[(size_t)row * 128 + j] = hl;
    }
}

// ---------------- final: out[b] = mean(hq[2b], hq[2b+1]) . mean_support ----------------
__global__ void k_final(float* __restrict__ out) {
    __shared__ float ms[128];
    int t = threadIdx.x;
    if (t < 128) ms[t] = d_MS[t];
    __syncthreads();
    int b = blockIdx.x * 8 + (t >> 5);
    int lane = t & 31;
    const float* q0 = d_q  + (size_t)b * 256;
    const float* h0 = d_hl + (size_t)b * 256;
    int j = lane * 4;
    float4 qa = *(const float4*)(q0 + j);
    float4 qb = *(const float4*)(q0 + 128 + j);
    float4 ha = *(const float4*)(h0 + j);
    float4 hb = *(const float4*)(h0 + 128 + j);
    float4 m4 = *(const float4*)(ms + j);
    float p = 0.5f * ((qa.x + ha.x + qb.x + hb.x) * m4.x +
                      (qa.y + ha.y + qb.y + hb.y) * m4.y +
                      (qa.z + ha.z + qb.z + hb.z) * m4.z +
                      (qa.w + ha.w + qb.w + hb.w) * m4.w);
    #pragma unroll
    for (int o = 16; o; o >>= 1) p += __shfl_xor_sync(0xffffffffu, p, o);
    if (lane == 0) out[b] = p;
}

// ---------------- launcher ----------------
extern "C" void kernel_launch(void* const* d_in, const int* in_sizes, int n_in,
                              void* d_out, int out_size) {
    const int*   qp  = (const int*)d_in[0];
    const int*   sp  = (const int*)d_in[1];
    const float* emb = (const float*)d_in[2];
    const float* gW  = (const float*)d_in[3];
    const float* gb  = (const float*)d_in[4];
    const float* p1W = (const float*)d_in[5];
    const float* p1b = (const float*)d_in[6];
    const float* p2W = (const float*)d_in[7];
    const float* p2b = (const float*)d_in[8];
    const float* lng = (const float*)d_in[9];
    const float* lnb = (const float*)d_in[10];
    const float* Wih = (const float*)d_in[11];
    const float* Whh = (const float*)d_in[12];
    const float* bih = (const float*)d_in[13];
    const float* bhh = (const float*)d_in[14];
    float* out = (float*)d_out;

    static int attr_set = 0;
    if (!attr_set) {
        cudaFuncSetAttribute(k_gates, cudaFuncAttributeMaxDynamicSharedMemorySize, SMEM_GATES);
        attr_set = 1;
    }

    k_wsum<<<512, 256>>>(Wih, Whh, bih, bhh);
    k_support<<<5, 256>>>(sp, emb, gW, gb, p1W, p1b, p2W, p2b, lng, lnb);
    k_s2mean<<<21, 128>>>(Whh);
    k_gather<<<NQ / 8, 256>>>(qp, emb);

    // step 0: gates = q@Wih.T + b  (hl slot holds -q), no attn
    k_gates<<<NQ / 128, 256, SMEM_GATES>>>(0);
    k_lstm<<<NQ / 8, 256>>>(1);

    // steps 1,2: gates = q@Wc.T + hl@W1.T + b + attn@S2
    k_gates<<<NQ / 128, 256, SMEM_GATES>>>(1);
    k_lstm<<<NQ / 8, 256>>>(0);
    k_gates<<<NQ / 128, 256, SMEM_GATES>>>(1);
    k_lstm<<<NQ / 8, 256>>>(0);

    // step 3 (last)
    k_gates<<<NQ / 128, 256, SMEM_GATES>>>(1);
    k_lstm_last<<<NQ / 8, 256>>>();

    k_final<<<16384 / 8, 256>>>(out);
}